// round 10
// baseline (speedup 1.0000x reference)
#include <cuda_runtime.h>
#include <cstdint>

#define BATCH 8192
#define NIN   3072
#define NOUT  512
#define EPSF  1e-20f
#define NITER 5
#define RPB   8    // batch rows per block
#define RP    4    // row-pairs per block (RPB/2)
#define T     256  // threads (8 warps)
#define NWARP 8
#define NTILE 8    // n-rows per phase-2 pass
#define RH    4    // rows per phase-2 half-pass

// smem: ratio[RPB*NIN] f32 | h2[NOUT*RP] u64 (row-paired) | hred2[RP] u64 | xinv[RPB] f32
#define SMEM_BYTES (RPB*NIN*4 + NOUT*RP*8 + RP*8 + RPB*4)

// ---- Blackwell packed-fp32 helpers (f32x2 via PTX) -------------------------
__device__ __forceinline__ uint64_t pack2(float lo, float hi) {
    uint64_t r; asm("mov.b64 %0, {%1,%2};" : "=l"(r) : "f"(lo), "f"(hi)); return r;
}
__device__ __forceinline__ void unpack2(uint64_t v, float& lo, float& hi) {
    asm("mov.b64 {%0,%1}, %2;" : "=f"(lo), "=f"(hi) : "l"(v));
}
__device__ __forceinline__ void ffma2(uint64_t& d, uint64_t a, uint64_t b) {
    asm("fma.rn.f32x2 %0, %1, %2, %0;" : "+l"(d) : "l"(a), "l"(b));
}
__device__ __forceinline__ uint64_t mul2(uint64_t a, uint64_t b) {
    uint64_t d; asm("mul.rn.f32x2 %0, %1, %2;" : "=l"(d) : "l"(a), "l"(b)); return d;
}

// One block = RPB batch rows, fully self-contained 5-iteration recurrence in
// shared memory (single launch; multi-kernel handoff variant was broken).
__global__ __launch_bounds__(T, 2) void fused_nnmf_kernel(
    const float* __restrict__ x,   // [BATCH, NIN]
    const float* __restrict__ W,   // [NOUT, NIN] row-major
    const float* __restrict__ h0,  // [NOUT]
    float* __restrict__ out        // [BATCH, NOUT]
) {
    extern __shared__ float smem[];
    float*    ratio = smem;                                    // 96 KB
    uint64_t* h2    = (uint64_t*)(smem + RPB * NIN);           // 16 KB, [NOUT][RP]
    uint64_t* hred2 = h2 + NOUT * RP;                          // [RP]
    float*    xinv  = (float*)(hred2 + RP);                    // [RPB]

    const int tid  = threadIdx.x;
    const int lane = tid & 31;
    const int warp = tid >> 5;
    const int r0   = blockIdx.x * RPB;

    // init h2[n][p] = (h0[n], h0[n])
    for (int i = tid; i < NOUT * RP; i += T) {
        float v = h0[i >> 2];
        h2[i] = pack2(v, v);
    }

    // per-row 1/(sum(x)+eps)
    for (int r = warp; r < RPB; r += NWARP) {
        const float* xrp = x + (size_t)(r0 + r) * NIN;
        float s = 0.f;
        for (int k = lane; k < NIN; k += 32) s += xrp[k];
        #pragma unroll
        for (int o = 16; o; o >>= 1) s += __shfl_xor_sync(~0u, s, o);
        if (lane == 0) xinv[r] = 1.0f / (s + EPSF);
    }
    __syncthreads();

    for (int iter = 0; iter < NITER; iter++) {
        // ---- Phase 1: denom[r][k] = sum_n h[r][n]*W[n][k]; ratio = xhat/denom
        // FFMA2 pair-dim = rows: d[k][p] = (denom[2p][k], denom[2p+1][k]).
        // h pairs come straight from LDS.128 (no packs); only W is dup-packed.
        #pragma unroll
        for (int g = 0; g < 3; g++) {
            const int kb = g * 1024 + tid * 4;
            uint64_t d[4][RP];
            #pragma unroll
            for (int k = 0; k < 4; k++)
                #pragma unroll
                for (int p = 0; p < RP; p++) d[k][p] = 0ull;

            const float* wp = W + kb;
            float4 wa[4], wb[4];
            #pragma unroll
            for (int j = 0; j < 4; j++)
                wa[j] = *(const float4*)(wp + (size_t)j * NIN);

            for (int n4 = 0; n4 < NOUT; n4 += 4) {
                if (n4 + 4 < NOUT) {
                    #pragma unroll
                    for (int j = 0; j < 4; j++)
                        wb[j] = *(const float4*)(wp + (size_t)(n4 + 4 + j) * NIN);
                }
                #pragma unroll
                for (int j = 0; j < 4; j++) {
                    ulonglong2 ha = *(const ulonglong2*)(h2 + (n4 + j) * RP);      // p0,p1
                    ulonglong2 hb = *(const ulonglong2*)(h2 + (n4 + j) * RP + 2);  // p2,p3
                    float4 w = wa[j];
                    uint64_t wd;
                    wd = pack2(w.x, w.x);
                    ffma2(d[0][0], ha.x, wd); ffma2(d[0][1], ha.y, wd);
                    ffma2(d[0][2], hb.x, wd); ffma2(d[0][3], hb.y, wd);
                    wd = pack2(w.y, w.y);
                    ffma2(d[1][0], ha.x, wd); ffma2(d[1][1], ha.y, wd);
                    ffma2(d[1][2], hb.x, wd); ffma2(d[1][3], hb.y, wd);
                    wd = pack2(w.z, w.z);
                    ffma2(d[2][0], ha.x, wd); ffma2(d[2][1], ha.y, wd);
                    ffma2(d[2][2], hb.x, wd); ffma2(d[2][3], hb.y, wd);
                    wd = pack2(w.w, w.w);
                    ffma2(d[3][0], ha.x, wd); ffma2(d[3][1], ha.y, wd);
                    ffma2(d[3][2], hb.x, wd); ffma2(d[3][3], hb.y, wd);
                }
                #pragma unroll
                for (int j = 0; j < 4; j++) wa[j] = wb[j];
            }

            // epilogue: unpack row-pairs, divide, store ratio
            #pragma unroll
            for (int p = 0; p < RP; p++) {
                float dlo[4], dhi[4];
                #pragma unroll
                for (int k = 0; k < 4; k++) unpack2(d[k][p], dlo[k], dhi[k]);
                const int rA = 2 * p, rB = 2 * p + 1;
                float4 xa = *(const float4*)(x + (size_t)(r0 + rA) * NIN + kb);
                float xia = xinv[rA];
                float4 oA;
                oA.x = __fdividef(xa.x * xia, dlo[0] + EPSF);
                oA.y = __fdividef(xa.y * xia, dlo[1] + EPSF);
                oA.z = __fdividef(xa.z * xia, dlo[2] + EPSF);
                oA.w = __fdividef(xa.w * xia, dlo[3] + EPSF);
                *(float4*)(ratio + rA * NIN + kb) = oA;
                float4 xb = *(const float4*)(x + (size_t)(r0 + rB) * NIN + kb);
                float xib = xinv[rB];
                float4 oB;
                oB.x = __fdividef(xb.x * xib, dhi[0] + EPSF);
                oB.y = __fdividef(xb.y * xib, dhi[1] + EPSF);
                oB.z = __fdividef(xb.z * xib, dhi[2] + EPSF);
                oB.w = __fdividef(xb.w * xib, dhi[3] + EPSF);
                *(float4*)(ratio + rB * NIN + kb) = oB;
            }
        }
        __syncthreads();

        // ---- Phase 2: t[r][n] = sum_k ratio[r][k]*W[n][k]; h *= (1+t)
        // NTILE=8 n per pass over RH=4 rows (two half-passes): crossbar halved.
        #pragma unroll
        for (int half = 0; half < 2; half++) {
            const int rbase = half * RH;
            for (int n0 = warp * NTILE; n0 < NOUT; n0 += NWARP * NTILE) {
                uint64_t acc[NTILE][RH];
                #pragma unroll
                for (int t = 0; t < NTILE; t++)
                    #pragma unroll
                    for (int r = 0; r < RH; r++) acc[t][r] = 0ull;

                #pragma unroll 2
                for (int i = 0; i < NIN / 128; i++) {
                    const int kk = i * 128 + lane * 4;
                    ulonglong2 w2[NTILE];
                    #pragma unroll
                    for (int t = 0; t < NTILE; t++)
                        w2[t] = *(const ulonglong2*)(W + (size_t)(n0 + t) * NIN + kk);
                    #pragma unroll
                    for (int r = 0; r < RH; r++) {
                        ulonglong2 rv = *(const ulonglong2*)(ratio + (rbase + r) * NIN + kk);
                        #pragma unroll
                        for (int t = 0; t < NTILE; t++) {
                            ffma2(acc[t][r], rv.x, w2[t].x);
                            ffma2(acc[t][r], rv.y, w2[t].y);
                        }
                    }
                }

                #pragma unroll
                for (int t = 0; t < NTILE; t++) {
                    float s[RH];
                    #pragma unroll
                    for (int r = 0; r < RH; r++) {
                        float lo, hi;
                        unpack2(acc[t][r], lo, hi);
                        s[r] = lo + hi;
                        #pragma unroll
                        for (int o = 16; o; o >>= 1)
                            s[r] += __shfl_xor_sync(~0u, s[r], o);
                    }
                    if (lane == 0) {
                        const int idx = (n0 + t) * RP + half * 2;
                        h2[idx]     = mul2(h2[idx],     pack2(1.0f + s[0], 1.0f + s[1]));
                        h2[idx + 1] = mul2(h2[idx + 1], pack2(1.0f + s[2], 1.0f + s[3]));
                    }
                }
            }
        }
        __syncthreads();

        // ---- normalize h rows (paired)
        for (int p = warp; p < RP; p += NWARP) {
            float slo = 0.f, shi = 0.f;
            for (int n = lane; n < NOUT; n += 32) {
                float a, b;
                unpack2(h2[n * RP + p], a, b);
                slo += a; shi += b;
            }
            #pragma unroll
            for (int o = 16; o; o >>= 1) {
                slo += __shfl_xor_sync(~0u, slo, o);
                shi += __shfl_xor_sync(~0u, shi, o);
            }
            if (lane == 0)
                hred2[p] = pack2(1.0f / (slo + EPSF), 1.0f / (shi + EPSF));
        }
        __syncthreads();
        for (int i = tid; i < NOUT * RP; i += T)
            h2[i] = mul2(h2[i], hred2[i & 3]);
        __syncthreads();
    }

    // write result (unpack row-pairs)
    for (int i = tid; i < NOUT * RP; i += T) {
        const int n = i >> 2, p = i & 3;
        float a, b;
        unpack2(h2[i], a, b);
        out[(size_t)(r0 + 2 * p) * NOUT + n]     = a;
        out[(size_t)(r0 + 2 * p + 1) * NOUT + n] = b;
    }
}

extern "C" void kernel_launch(void* const* d_in, const int* in_sizes, int n_in,
                              void* d_out, int out_size) {
    // Identify inputs by element count — immune to metadata ordering.
    const float* x = nullptr;   // BATCH*NIN = 25165824
    const float* W = nullptr;   // NOUT*NIN  = 1572864
    const float* h0 = nullptr;  // NOUT      = 512
    for (int i = 0; i < n_in; i++) {
        if (in_sizes[i] == BATCH * NIN)      x  = (const float*)d_in[i];
        else if (in_sizes[i] == NOUT * NIN)  W  = (const float*)d_in[i];
        else if (in_sizes[i] == NOUT)        h0 = (const float*)d_in[i];
    }
    float* out = (float*)d_out;  // [BATCH, NOUT]

    cudaFuncSetAttribute(fused_nnmf_kernel,
                         cudaFuncAttributeMaxDynamicSharedMemorySize, SMEM_BYTES);

    fused_nnmf_kernel<<<BATCH / RPB, T, SMEM_BYTES>>>(x, W, h0, out);
}

// round 11
// speedup vs baseline: 1.2190x; 1.2190x over previous
#include <cuda_runtime.h>
#include <cstdint>

#define BATCH 8192
#define NIN   3072
#define NOUT  512
#define EPSF  1e-20f
#define NITER 5
#define RPB   8    // batch rows per block
#define RP    4    // row-pairs per block (RPB/2)
#define T     256  // threads (8 warps)
#define NWARP 8
#define NTILE 4    // n-rows per phase-2 pass (R9's proven L2-balanced config)

// smem: ratio[RPB*NIN] f32 | h2[NOUT*RP] u64 (row-paired) | hred2[RP] u64 | xinv[RPB] f32
#define SMEM_BYTES (RPB*NIN*4 + NOUT*RP*8 + RP*8 + RPB*4)

// ---- Blackwell packed-fp32 helpers (f32x2 via PTX) -------------------------
__device__ __forceinline__ uint64_t pack2(float lo, float hi) {
    uint64_t r; asm("mov.b64 %0, {%1,%2};" : "=l"(r) : "f"(lo), "f"(hi)); return r;
}
__device__ __forceinline__ void unpack2(uint64_t v, float& lo, float& hi) {
    asm("mov.b64 {%0,%1}, %2;" : "=f"(lo), "=f"(hi) : "l"(v));
}
__device__ __forceinline__ void ffma2(uint64_t& d, uint64_t a, uint64_t b) {
    asm("fma.rn.f32x2 %0, %1, %2, %0;" : "+l"(d) : "l"(a), "l"(b));
}
__device__ __forceinline__ uint64_t mul2(uint64_t a, uint64_t b) {
    uint64_t d; asm("mul.rn.f32x2 %0, %1, %2;" : "=l"(d) : "l"(a), "l"(b)); return d;
}

// One block = RPB batch rows, fully self-contained 5-iteration recurrence in
// shared memory (single launch; multi-kernel handoff variant was broken).
__global__ __launch_bounds__(T, 2) void fused_nnmf_kernel(
    const float* __restrict__ x,   // [BATCH, NIN]
    const float* __restrict__ W,   // [NOUT, NIN] row-major
    const float* __restrict__ h0,  // [NOUT]
    float* __restrict__ out        // [BATCH, NOUT]
) {
    extern __shared__ float smem[];
    float*    ratio = smem;                                    // 96 KB
    uint64_t* h2    = (uint64_t*)(smem + RPB * NIN);           // 16 KB, [NOUT][RP]
    uint64_t* hred2 = h2 + NOUT * RP;                          // [RP]
    float*    xinv  = (float*)(hred2 + RP);                    // [RPB]

    const int tid  = threadIdx.x;
    const int lane = tid & 31;
    const int warp = tid >> 5;
    const int r0   = blockIdx.x * RPB;

    // init h2[n][p] = (h0[n], h0[n])
    for (int i = tid; i < NOUT * RP; i += T) {
        float v = h0[i >> 2];
        h2[i] = pack2(v, v);
    }

    // per-row 1/(sum(x)+eps)
    for (int r = warp; r < RPB; r += NWARP) {
        const float* xrp = x + (size_t)(r0 + r) * NIN;
        float s = 0.f;
        for (int k = lane; k < NIN; k += 32) s += xrp[k];
        #pragma unroll
        for (int o = 16; o; o >>= 1) s += __shfl_xor_sync(~0u, s, o);
        if (lane == 0) xinv[r] = 1.0f / (s + EPSF);
    }
    __syncthreads();

    for (int iter = 0; iter < NITER; iter++) {
        // ---- Phase 1: denom[r][k] = sum_n h[r][n]*W[n][k]; ratio = xhat/denom
        // FFMA2 pair-dim = rows: d[k][p] = (denom[2p][k], denom[2p+1][k]).
        // h pairs straight from LDS.128 (no packs); only W is dup-packed.
        #pragma unroll
        for (int g = 0; g < 3; g++) {
            const int kb = g * 1024 + tid * 4;
            uint64_t d[4][RP];
            #pragma unroll
            for (int k = 0; k < 4; k++)
                #pragma unroll
                for (int p = 0; p < RP; p++) d[k][p] = 0ull;

            const float* wp = W + kb;
            float4 wa[4], wb[4];
            #pragma unroll
            for (int j = 0; j < 4; j++)
                wa[j] = *(const float4*)(wp + (size_t)j * NIN);

            for (int n4 = 0; n4 < NOUT; n4 += 4) {
                if (n4 + 4 < NOUT) {
                    #pragma unroll
                    for (int j = 0; j < 4; j++)
                        wb[j] = *(const float4*)(wp + (size_t)(n4 + 4 + j) * NIN);
                }
                #pragma unroll
                for (int j = 0; j < 4; j++) {
                    ulonglong2 ha = *(const ulonglong2*)(h2 + (n4 + j) * RP);      // p0,p1
                    ulonglong2 hb = *(const ulonglong2*)(h2 + (n4 + j) * RP + 2);  // p2,p3
                    float4 w = wa[j];
                    uint64_t wd;
                    wd = pack2(w.x, w.x);
                    ffma2(d[0][0], ha.x, wd); ffma2(d[0][1], ha.y, wd);
                    ffma2(d[0][2], hb.x, wd); ffma2(d[0][3], hb.y, wd);
                    wd = pack2(w.y, w.y);
                    ffma2(d[1][0], ha.x, wd); ffma2(d[1][1], ha.y, wd);
                    ffma2(d[1][2], hb.x, wd); ffma2(d[1][3], hb.y, wd);
                    wd = pack2(w.z, w.z);
                    ffma2(d[2][0], ha.x, wd); ffma2(d[2][1], ha.y, wd);
                    ffma2(d[2][2], hb.x, wd); ffma2(d[2][3], hb.y, wd);
                    wd = pack2(w.w, w.w);
                    ffma2(d[3][0], ha.x, wd); ffma2(d[3][1], ha.y, wd);
                    ffma2(d[3][2], hb.x, wd); ffma2(d[3][3], hb.y, wd);
                }
                #pragma unroll
                for (int j = 0; j < 4; j++) wa[j] = wb[j];
            }

            // epilogue: unpack row-pairs, divide, store ratio
            #pragma unroll
            for (int p = 0; p < RP; p++) {
                float dlo[4], dhi[4];
                #pragma unroll
                for (int k = 0; k < 4; k++) unpack2(d[k][p], dlo[k], dhi[k]);
                const int rA = 2 * p, rB = 2 * p + 1;
                float4 xa = *(const float4*)(x + (size_t)(r0 + rA) * NIN + kb);
                float xia = xinv[rA];
                float4 oA;
                oA.x = __fdividef(xa.x * xia, dlo[0] + EPSF);
                oA.y = __fdividef(xa.y * xia, dlo[1] + EPSF);
                oA.z = __fdividef(xa.z * xia, dlo[2] + EPSF);
                oA.w = __fdividef(xa.w * xia, dlo[3] + EPSF);
                *(float4*)(ratio + rA * NIN + kb) = oA;
                float4 xb = *(const float4*)(x + (size_t)(r0 + rB) * NIN + kb);
                float xib = xinv[rB];
                float4 oB;
                oB.x = __fdividef(xb.x * xib, dhi[0] + EPSF);
                oB.y = __fdividef(xb.y * xib, dhi[1] + EPSF);
                oB.z = __fdividef(xb.z * xib, dhi[2] + EPSF);
                oB.w = __fdividef(xb.w * xib, dhi[3] + EPSF);
                *(float4*)(ratio + rB * NIN + kb) = oB;
            }
        }
        __syncthreads();

        // ---- Phase 2 (R9's proven config): t[r][n] = sum_k ratio[r][k]*W[n][k]
        // NTILE=4 n per pass over ALL 8 rows: W streamed once per block-iter.
        for (int n0 = warp * NTILE; n0 < NOUT; n0 += NWARP * NTILE) {
            uint64_t acc[NTILE][RPB];
            #pragma unroll
            for (int t = 0; t < NTILE; t++)
                #pragma unroll
                for (int r = 0; r < RPB; r++) acc[t][r] = 0ull;

            #pragma unroll 2
            for (int i = 0; i < NIN / 128; i++) {
                const int kk = i * 128 + lane * 4;
                ulonglong2 w2[NTILE];
                #pragma unroll
                for (int t = 0; t < NTILE; t++)
                    w2[t] = *(const ulonglong2*)(W + (size_t)(n0 + t) * NIN + kk);
                #pragma unroll
                for (int r = 0; r < RPB; r++) {
                    ulonglong2 rv = *(const ulonglong2*)(ratio + r * NIN + kk);
                    #pragma unroll
                    for (int t = 0; t < NTILE; t++) {
                        ffma2(acc[t][r], rv.x, w2[t].x);
                        ffma2(acc[t][r], rv.y, w2[t].y);
                    }
                }
            }

            #pragma unroll
            for (int t = 0; t < NTILE; t++) {
                float s[RPB];
                #pragma unroll
                for (int r = 0; r < RPB; r++) {
                    float lo, hi;
                    unpack2(acc[t][r], lo, hi);
                    s[r] = lo + hi;
                    #pragma unroll
                    for (int o = 16; o; o >>= 1)
                        s[r] += __shfl_xor_sync(~0u, s[r], o);
                }
                if (lane == 0) {
                    const int idx = (n0 + t) * RP;
                    #pragma unroll
                    for (int p = 0; p < RP; p++)
                        h2[idx + p] = mul2(h2[idx + p],
                                           pack2(1.0f + s[2 * p], 1.0f + s[2 * p + 1]));
                }
            }
        }
        __syncthreads();

        // ---- normalize h rows (paired)
        for (int p = warp; p < RP; p += NWARP) {
            float slo = 0.f, shi = 0.f;
            for (int n = lane; n < NOUT; n += 32) {
                float a, b;
                unpack2(h2[n * RP + p], a, b);
                slo += a; shi += b;
            }
            #pragma unroll
            for (int o = 16; o; o >>= 1) {
                slo += __shfl_xor_sync(~0u, slo, o);
                shi += __shfl_xor_sync(~0u, shi, o);
            }
            if (lane == 0)
                hred2[p] = pack2(1.0f / (slo + EPSF), 1.0f / (shi + EPSF));
        }
        __syncthreads();
        for (int i = tid; i < NOUT * RP; i += T)
            h2[i] = mul2(h2[i], hred2[i & 3]);
        __syncthreads();
    }

    // write result (unpack row-pairs)
    for (int i = tid; i < NOUT * RP; i += T) {
        const int n = i >> 2, p = i & 3;
        float a, b;
        unpack2(h2[i], a, b);
        out[(size_t)(r0 + 2 * p) * NOUT + n]     = a;
        out[(size_t)(r0 + 2 * p + 1) * NOUT + n] = b;
    }
}

extern "C" void kernel_launch(void* const* d_in, const int* in_sizes, int n_in,
                              void* d_out, int out_size) {
    // Identify inputs by element count — immune to metadata ordering.
    const float* x = nullptr;   // BATCH*NIN = 25165824
    const float* W = nullptr;   // NOUT*NIN  = 1572864
    const float* h0 = nullptr;  // NOUT      = 512
    for (int i = 0; i < n_in; i++) {
        if (in_sizes[i] == BATCH * NIN)      x  = (const float*)d_in[i];
        else if (in_sizes[i] == NOUT * NIN)  W  = (const float*)d_in[i];
        else if (in_sizes[i] == NOUT)        h0 = (const float*)d_in[i];
    }
    float* out = (float*)d_out;  // [BATCH, NOUT]

    cudaFuncSetAttribute(fused_nnmf_kernel,
                         cudaFuncAttributeMaxDynamicSharedMemorySize, SMEM_BYTES);

    fused_nnmf_kernel<<<BATCH / RPB, T, SMEM_BYTES>>>(x, W, h0, out);
}